// round 2
// baseline (speedup 1.0000x reference)
#include <cuda_runtime.h>
#include <cuda_bf16.h>

// AnisotropicDistance:
// out[b,i,j] = alpha_i * max(||p_i-p_j||^2 + along^2*(||t_i||^2 - 2), 0) + beta_i * along^2
// where along = (p_i - p_j) . t_i = (p_i.t_i) - (p_j.t_i)
// alpha_i = 2*(1+lin_i), beta_i = 0.5*(1-lin_i)
//
// Strategy: store-bandwidth-bound (536 MB out). SoA precompute + 2D-tiled main
// kernel (TI=16 rows of i per block, 1024 j per block, float4 stores).

#define MAX_PTS 32768  // B*N max supported (actual: 2*8192 = 16384)

// Per-point scratch (SoA). j-side data:
__device__ float g_px[MAX_PTS];
__device__ float g_py[MAX_PTS];
__device__ float g_pz[MAX_PTS];
__device__ float g_sq[MAX_PTS];
// i-side data:
__device__ float g_tx[MAX_PTS];
__device__ float g_ty[MAX_PTS];
__device__ float g_tz[MAX_PTS];
__device__ float g_pdself[MAX_PTS];  // p_i . t_i
__device__ float g_c1[MAX_PTS];      // ||t_i||^2 - 2
__device__ float g_alpha[MAX_PTS];
__device__ float g_beta[MAX_PTS];

__global__ void precompute_kernel(const float* __restrict__ points,
                                  const float* __restrict__ pdir,
                                  const float* __restrict__ lin,
                                  int total) {
    int idx = blockIdx.x * blockDim.x + threadIdx.x;
    if (idx >= total) return;
    float px = points[idx * 3 + 0];
    float py = points[idx * 3 + 1];
    float pz = points[idx * 3 + 2];
    float tx = pdir[idx * 3 + 0];
    float ty = pdir[idx * 3 + 1];
    float tz = pdir[idx * 3 + 2];
    float l  = lin[idx];

    g_px[idx] = px; g_py[idx] = py; g_pz[idx] = pz;
    g_sq[idx] = fmaf(px, px, fmaf(py, py, pz * pz));
    g_tx[idx] = tx; g_ty[idx] = ty; g_tz[idx] = tz;
    g_pdself[idx] = fmaf(px, tx, fmaf(py, ty, pz * tz));
    g_c1[idx] = fmaf(tx, tx, fmaf(ty, ty, tz * tz)) - 2.0f;
    g_alpha[idx] = 2.0f * (1.0f + l);
    g_beta[idx]  = 0.5f * (1.0f - l);
}

#define TI 16          // i-rows per block
#define TPB 256        // threads per block
#define JV 4           // j per thread (float4)
// block covers TPB*JV = 1024 j columns

__global__ __launch_bounds__(TPB) void aniso_main_kernel(float* __restrict__ out, int N) {
    __shared__ float s_pix[TI], s_piy[TI], s_piz[TI];
    __shared__ float s_tx[TI],  s_ty[TI],  s_tz[TI];
    __shared__ float s_pds[TI], s_c1[TI], s_al[TI], s_be[TI], s_sqi[TI];

    const int b  = blockIdx.z;
    const int i0 = blockIdx.y * TI;
    const int j4 = blockIdx.x * TPB + threadIdx.x;   // float4 index in j
    const int j  = j4 * JV;
    const int base = b * N;                          // point index base

    // Cooperative load of per-i constants
    if (threadIdx.x < TI) {
        int gi = base + i0 + threadIdx.x;
        s_pix[threadIdx.x] = g_px[gi];
        s_piy[threadIdx.x] = g_py[gi];
        s_piz[threadIdx.x] = g_pz[gi];
        s_tx[threadIdx.x]  = g_tx[gi];
        s_ty[threadIdx.x]  = g_ty[gi];
        s_tz[threadIdx.x]  = g_tz[gi];
        s_pds[threadIdx.x] = g_pdself[gi];
        s_c1[threadIdx.x]  = g_c1[gi];
        s_al[threadIdx.x]  = g_alpha[gi];
        s_be[threadIdx.x]  = g_beta[gi];
        s_sqi[threadIdx.x] = g_sq[gi];
    }
    __syncthreads();

    if (j >= N) return;

    // Load j-side data (float4, coalesced; L2-resident)
    const float4 pjx = reinterpret_cast<const float4*>(g_px + base)[j4];
    const float4 pjy = reinterpret_cast<const float4*>(g_py + base)[j4];
    const float4 pjz = reinterpret_cast<const float4*>(g_pz + base)[j4];
    const float4 sqj = reinterpret_cast<const float4*>(g_sq + base)[j4];

    float* orow = out + ((size_t)b * N + i0) * N + j;

    #pragma unroll
    for (int ii = 0; ii < TI; ii++) {
        const float tx = s_tx[ii], ty = s_ty[ii], tz = s_tz[ii];
        const float pix = s_pix[ii], piy = s_piy[ii], piz = s_piz[ii];
        const float pds = s_pds[ii], c1 = s_c1[ii];
        const float al = s_al[ii], be = s_be[ii];
        const float sqsum_base = s_sqi[ii];

        float4 o;
        {
            // lane 0
            float cr = fmaf(pjx.x, tx, fmaf(pjy.x, ty, pjz.x * tz));
            float along = pds - cr;
            float a2 = along * along;
            float dotp = fmaf(pjx.x, pix, fmaf(pjy.x, piy, pjz.x * piz));
            float sqd = fmaf(-2.0f, dotp, sqsum_base + sqj.x);
            float ns = fmaxf(fmaf(a2, c1, sqd), 0.0f);
            o.x = fmaf(al, ns, be * a2);
        }
        {
            float cr = fmaf(pjx.y, tx, fmaf(pjy.y, ty, pjz.y * tz));
            float along = pds - cr;
            float a2 = along * along;
            float dotp = fmaf(pjx.y, pix, fmaf(pjy.y, piy, pjz.y * piz));
            float sqd = fmaf(-2.0f, dotp, sqsum_base + sqj.y);
            float ns = fmaxf(fmaf(a2, c1, sqd), 0.0f);
            o.y = fmaf(al, ns, be * a2);
        }
        {
            float cr = fmaf(pjx.z, tx, fmaf(pjy.z, ty, pjz.z * tz));
            float along = pds - cr;
            float a2 = along * along;
            float dotp = fmaf(pjx.z, pix, fmaf(pjy.z, piy, pjz.z * piz));
            float sqd = fmaf(-2.0f, dotp, sqsum_base + sqj.z);
            float ns = fmaxf(fmaf(a2, c1, sqd), 0.0f);
            o.z = fmaf(al, ns, be * a2);
        }
        {
            float cr = fmaf(pjx.w, tx, fmaf(pjy.w, ty, pjz.w * tz));
            float along = pds - cr;
            float a2 = along * along;
            float dotp = fmaf(pjx.w, pix, fmaf(pjy.w, piy, pjz.w * piz));
            float sqd = fmaf(-2.0f, dotp, sqsum_base + sqj.w);
            float ns = fmaxf(fmaf(a2, c1, sqd), 0.0f);
            o.w = fmaf(al, ns, be * a2);
        }
        *reinterpret_cast<float4*>(orow) = o;
        orow += N;
    }
}

extern "C" void kernel_launch(void* const* d_in, const int* in_sizes, int n_in,
                              void* d_out, int out_size) {
    const float* points = (const float*)d_in[0];
    const float* pdir   = (const float*)d_in[1];
    const float* lin    = (const float*)d_in[2];
    float* out = (float*)d_out;

    const int total = in_sizes[0] / 3;      // B*N points
    const int N = (int)((long long)out_size / total);  // out = B*N*N
    const int B = total / N;

    precompute_kernel<<<(total + 255) / 256, 256>>>(points, pdir, lin, total);

    dim3 grid((N + TPB * JV - 1) / (TPB * JV), (N + TI - 1) / TI, B);
    aniso_main_kernel<<<grid, TPB>>>(out, N);
}

// round 4
// speedup vs baseline: 1.0210x; 1.0210x over previous
#include <cuda_runtime.h>
#include <cuda_bf16.h>

// AnisotropicDistance:
// out[b,i,j] = alpha_i * max(||p_i-p_j||^2 + along^2*(||t_i||^2 - 2), 0) + beta_i * along^2
// along = (p_i.t_i) - (p_j.t_i)
//
// R2: packed f32x2 math (fma.rn.f32x2) with pre-duplicated / pre-negated per-i
// constants so the hot loop has zero pack overhead. alpha>0 lets us fold the
// max into the alu pipe: alpha*max(ns,0) = max(alpha*ns, 0).

#define MAX_PTS 32768  // B*N max supported (actual: 2*8192 = 16384)

typedef unsigned long long ull;

// j-side SoA:
__device__ float g_px[MAX_PTS];
__device__ float g_py[MAX_PTS];
__device__ float g_pz[MAX_PTS];
__device__ float g_sq[MAX_PTS];
// i-side constants, duplicated into both halves of a b64 (f32x2 layout):
__device__ ull g2_ntx[MAX_PTS];   // (-tx, -tx)
__device__ ull g2_nty[MAX_PTS];
__device__ ull g2_ntz[MAX_PTS];
__device__ ull g2_pds[MAX_PTS];   // (p_i.t_i) dup
__device__ ull g2_npx[MAX_PTS];   // (-2*pix) dup
__device__ ull g2_npy[MAX_PTS];
__device__ ull g2_npz[MAX_PTS];
__device__ ull g2_c1[MAX_PTS];    // (||t||^2 - 2) dup
__device__ ull g2_al[MAX_PTS];    // alpha dup
__device__ ull g2_be[MAX_PTS];    // beta dup
__device__ ull g2_sqi[MAX_PTS];   // ||p_i||^2 dup

#define FMA2(d, a, b, c) asm("fma.rn.f32x2 %0, %1, %2, %3;" : "=l"(d) : "l"(a), "l"(b), "l"(c))
#define MUL2(d, a, b)    asm("mul.rn.f32x2 %0, %1, %2;"     : "=l"(d) : "l"(a), "l"(b))
#define ADD2(d, a, b)    asm("add.rn.f32x2 %0, %1, %2;"     : "=l"(d) : "l"(a), "l"(b))
#define PACK2(d, lo, hi) asm("mov.b64 %0, {%1, %2};"        : "=l"(d) : "f"(lo), "f"(hi))
#define UNPACK2(lo, hi, s) asm("mov.b64 {%0, %1}, %2;"      : "=f"(lo), "=f"(hi) : "l"(s))

__device__ __forceinline__ ull dup_f(float v) {
    ull d; PACK2(d, v, v); return d;
}

__global__ void precompute_kernel(const float* __restrict__ points,
                                  const float* __restrict__ pdir,
                                  const float* __restrict__ lin,
                                  int total) {
    int idx = blockIdx.x * blockDim.x + threadIdx.x;
    if (idx >= total) return;
    float px = points[idx * 3 + 0];
    float py = points[idx * 3 + 1];
    float pz = points[idx * 3 + 2];
    float tx = pdir[idx * 3 + 0];
    float ty = pdir[idx * 3 + 1];
    float tz = pdir[idx * 3 + 2];
    float l  = lin[idx];

    g_px[idx] = px; g_py[idx] = py; g_pz[idx] = pz;
    float sq = fmaf(px, px, fmaf(py, py, pz * pz));
    g_sq[idx] = sq;

    g2_ntx[idx] = dup_f(-tx);
    g2_nty[idx] = dup_f(-ty);
    g2_ntz[idx] = dup_f(-tz);
    g2_pds[idx] = dup_f(fmaf(px, tx, fmaf(py, ty, pz * tz)));
    g2_npx[idx] = dup_f(-2.0f * px);
    g2_npy[idx] = dup_f(-2.0f * py);
    g2_npz[idx] = dup_f(-2.0f * pz);
    g2_c1[idx]  = dup_f(fmaf(tx, tx, fmaf(ty, ty, tz * tz)) - 2.0f);
    g2_al[idx]  = dup_f(2.0f * (1.0f + l));
    g2_be[idx]  = dup_f(0.5f * (1.0f - l));
    g2_sqi[idx] = dup_f(sq);
}

#define TI 16          // i-rows per block
#define TPB 256        // threads per block
#define JV 4           // j per thread (one float4 store)
// block covers TPB*JV = 1024 j columns

__global__ __launch_bounds__(TPB) void aniso_main_kernel(float* __restrict__ out, int N) {
    __shared__ ull s_ntx[TI], s_nty[TI], s_ntz[TI], s_pds[TI];
    __shared__ ull s_npx[TI], s_npy[TI], s_npz[TI];
    __shared__ ull s_c1[TI], s_al[TI], s_be[TI], s_sqi[TI];

    const int b  = blockIdx.z;
    const int i0 = blockIdx.y * TI;
    const int j4 = blockIdx.x * TPB + threadIdx.x;   // float4 index in j
    const int j  = j4 * JV;
    const int base = b * N;

    if (threadIdx.x < TI) {
        int gi = base + i0 + threadIdx.x;
        s_ntx[threadIdx.x] = g2_ntx[gi];
        s_nty[threadIdx.x] = g2_nty[gi];
        s_ntz[threadIdx.x] = g2_ntz[gi];
        s_pds[threadIdx.x] = g2_pds[gi];
        s_npx[threadIdx.x] = g2_npx[gi];
        s_npy[threadIdx.x] = g2_npy[gi];
        s_npz[threadIdx.x] = g2_npz[gi];
        s_c1[threadIdx.x]  = g2_c1[gi];
        s_al[threadIdx.x]  = g2_al[gi];
        s_be[threadIdx.x]  = g2_be[gi];
        s_sqi[threadIdx.x] = g2_sqi[gi];
    }
    __syncthreads();

    if (j >= N) return;

    // j-side loads (coalesced float4, L2-resident), packed into b64 pairs once
    const float4 pjx = reinterpret_cast<const float4*>(g_px + base)[j4];
    const float4 pjy = reinterpret_cast<const float4*>(g_py + base)[j4];
    const float4 pjz = reinterpret_cast<const float4*>(g_pz + base)[j4];
    const float4 sqj = reinterpret_cast<const float4*>(g_sq + base)[j4];

    ull pjx01, pjx23, pjy01, pjy23, pjz01, pjz23, sqj01, sqj23;
    PACK2(pjx01, pjx.x, pjx.y); PACK2(pjx23, pjx.z, pjx.w);
    PACK2(pjy01, pjy.x, pjy.y); PACK2(pjy23, pjy.z, pjy.w);
    PACK2(pjz01, pjz.x, pjz.y); PACK2(pjz23, pjz.z, pjz.w);
    PACK2(sqj01, sqj.x, sqj.y); PACK2(sqj23, sqj.z, sqj.w);

    float* orow = out + ((size_t)b * N + i0) * N + j;

    #pragma unroll
    for (int ii = 0; ii < TI; ii++) {
        const ull ntx = s_ntx[ii], nty = s_nty[ii], ntz = s_ntz[ii], pds = s_pds[ii];
        const ull npx = s_npx[ii], npy = s_npy[ii], npz = s_npz[ii];
        const ull c1 = s_c1[ii], al = s_al[ii], be = s_be[ii], sqi = s_sqi[ii];

        float4 o;

        // ---- pair 0 (j, j+1) ----
        {
            ull u, a2, s, t1, t2;
            FMA2(u, pjz01, ntz, pds);          // pds - pjz*tz
            FMA2(u, pjy01, nty, u);
            FMA2(u, pjx01, ntx, u);            // along
            MUL2(a2, u, u);                    // along^2
            FMA2(s, pjz01, npz, sqi);          // sqi - 2*pjz*piz
            FMA2(s, pjy01, npy, s);
            FMA2(s, pjx01, npx, s);            // sqi - 2*(pj.pi)
            FMA2(s, a2, c1, s);                // + a2*(||t||^2-2)
            ADD2(s, s, sqj01);                 // + sqj  -> ns (pre-max)
            MUL2(t1, al, s);                   // alpha*ns
            MUL2(t2, be, a2);                  // beta*a2
            float t1x, t1y, t2x, t2y;
            UNPACK2(t1x, t1y, t1);
            UNPACK2(t2x, t2y, t2);
            o.x = fmaxf(t1x, 0.0f) + t2x;      // alpha>0: max(alpha*ns,0)=alpha*max(ns,0)
            o.y = fmaxf(t1y, 0.0f) + t2y;
        }
        // ---- pair 1 (j+2, j+3) ----
        {
            ull u, a2, s, t1, t2;
            FMA2(u, pjz23, ntz, pds);
            FMA2(u, pjy23, nty, u);
            FMA2(u, pjx23, ntx, u);
            MUL2(a2, u, u);
            FMA2(s, pjz23, npz, sqi);
            FMA2(s, pjy23, npy, s);
            FMA2(s, pjx23, npx, s);
            FMA2(s, a2, c1, s);
            ADD2(s, s, sqj23);
            MUL2(t1, al, s);
            MUL2(t2, be, a2);
            float t1x, t1y, t2x, t2y;
            UNPACK2(t1x, t1y, t1);
            UNPACK2(t2x, t2y, t2);
            o.z = fmaxf(t1x, 0.0f) + t2x;
            o.w = fmaxf(t1y, 0.0f) + t2y;
        }

        *reinterpret_cast<float4*>(orow) = o;
        orow += N;
    }
}

extern "C" void kernel_launch(void* const* d_in, const int* in_sizes, int n_in,
                              void* d_out, int out_size) {
    const float* points = (const float*)d_in[0];
    const float* pdir   = (const float*)d_in[1];
    const float* lin    = (const float*)d_in[2];
    float* out = (float*)d_out;

    const int total = in_sizes[0] / 3;                 // B*N points
    const int N = (int)((long long)out_size / total);  // out = B*N*N
    const int B = total / N;

    precompute_kernel<<<(total + 255) / 256, 256>>>(points, pdir, lin, total);

    dim3 grid((N + TPB * JV - 1) / (TPB * JV), (N + TI - 1) / TI, B);
    aniso_main_kernel<<<grid, TPB>>>(out, N);
}

// round 5
// speedup vs baseline: 1.0528x; 1.0311x over previous
#include <cuda_runtime.h>
#include <cuda_bf16.h>

// AnisotropicDistance:
// out[b,i,j] = alpha_i * max(||p_i-p_j||^2 + along^2*(||t_i||^2 - 2), 0) + beta_i * along^2
// along = (p_i.t_i) - (p_j.t_i)
//
// R4: per-i constants packed 2-per-16B -> LDS.128 x6 per iter (was LDS.64 x11);
// launch_bounds(256,4) for 50% occupancy; __stcs streaming stores.

#define MAX_PTS 32768  // B*N max supported (actual: 2*8192 = 16384)

typedef unsigned long long ull;

// j-side SoA:
__device__ float g_px[MAX_PTS];
__device__ float g_py[MAX_PTS];
__device__ float g_pz[MAX_PTS];
__device__ float g_sq[MAX_PTS];
// i-side constants, duplicated (v,v) into b64, packed 2 consts per ulonglong2:
// slot 0: (ntx, nty)   slot 1: (ntz, pds)   slot 2: (npx, npy)
// slot 3: (npz, c1)    slot 4: (al,  be)    slot 5: (sqi, sqi)
__device__ ulonglong2 g2c[MAX_PTS * 6];

#define FMA2(d, a, b, c) asm("fma.rn.f32x2 %0, %1, %2, %3;" : "=l"(d) : "l"(a), "l"(b), "l"(c))
#define MUL2(d, a, b)    asm("mul.rn.f32x2 %0, %1, %2;"     : "=l"(d) : "l"(a), "l"(b))
#define ADD2(d, a, b)    asm("add.rn.f32x2 %0, %1, %2;"     : "=l"(d) : "l"(a), "l"(b))
#define PACK2(d, lo, hi) asm("mov.b64 %0, {%1, %2};"        : "=l"(d) : "f"(lo), "f"(hi))
#define UNPACK2(lo, hi, s) asm("mov.b64 {%0, %1}, %2;"      : "=f"(lo), "=f"(hi) : "l"(s))

__device__ __forceinline__ ull dup_f(float v) {
    ull d; PACK2(d, v, v); return d;
}

__global__ void precompute_kernel(const float* __restrict__ points,
                                  const float* __restrict__ pdir,
                                  const float* __restrict__ lin,
                                  int total) {
    int idx = blockIdx.x * blockDim.x + threadIdx.x;
    if (idx >= total) return;
    float px = points[idx * 3 + 0];
    float py = points[idx * 3 + 1];
    float pz = points[idx * 3 + 2];
    float tx = pdir[idx * 3 + 0];
    float ty = pdir[idx * 3 + 1];
    float tz = pdir[idx * 3 + 2];
    float l  = lin[idx];

    g_px[idx] = px; g_py[idx] = py; g_pz[idx] = pz;
    float sq = fmaf(px, px, fmaf(py, py, pz * pz));
    g_sq[idx] = sq;

    ulonglong2 c;
    c.x = dup_f(-tx);                 c.y = dup_f(-ty);
    g2c[idx * 6 + 0] = c;
    c.x = dup_f(-tz);                 c.y = dup_f(fmaf(px, tx, fmaf(py, ty, pz * tz)));
    g2c[idx * 6 + 1] = c;
    c.x = dup_f(-2.0f * px);          c.y = dup_f(-2.0f * py);
    g2c[idx * 6 + 2] = c;
    c.x = dup_f(-2.0f * pz);          c.y = dup_f(fmaf(tx, tx, fmaf(ty, ty, tz * tz)) - 2.0f);
    g2c[idx * 6 + 3] = c;
    c.x = dup_f(2.0f * (1.0f + l));   c.y = dup_f(0.5f * (1.0f - l));
    g2c[idx * 6 + 4] = c;
    c.x = dup_f(sq);                  c.y = dup_f(sq);
    g2c[idx * 6 + 5] = c;
}

#define TI 16          // i-rows per block
#define TPB 256        // threads per block
#define JV 4           // j per thread (one float4 store)
// block covers TPB*JV = 1024 j columns

__global__ __launch_bounds__(TPB, 4) void aniso_main_kernel(float* __restrict__ out, int N) {
    __shared__ ulonglong2 s_c[TI * 6];

    const int b  = blockIdx.z;
    const int i0 = blockIdx.y * TI;
    const int j4 = blockIdx.x * TPB + threadIdx.x;   // float4 index in j
    const int j  = j4 * JV;
    const int base = b * N;

    if (threadIdx.x < TI * 6) {
        s_c[threadIdx.x] = g2c[(base + i0) * 6 + threadIdx.x];
    }
    __syncthreads();

    if (j >= N) return;

    // j-side loads (coalesced float4, L2-resident), packed into b64 pairs once
    const float4 pjx = reinterpret_cast<const float4*>(g_px + base)[j4];
    const float4 pjy = reinterpret_cast<const float4*>(g_py + base)[j4];
    const float4 pjz = reinterpret_cast<const float4*>(g_pz + base)[j4];
    const float4 sqj = reinterpret_cast<const float4*>(g_sq + base)[j4];

    ull pjx01, pjx23, pjy01, pjy23, pjz01, pjz23, sqj01, sqj23;
    PACK2(pjx01, pjx.x, pjx.y); PACK2(pjx23, pjx.z, pjx.w);
    PACK2(pjy01, pjy.x, pjy.y); PACK2(pjy23, pjy.z, pjy.w);
    PACK2(pjz01, pjz.x, pjz.y); PACK2(pjz23, pjz.z, pjz.w);
    PACK2(sqj01, sqj.x, sqj.y); PACK2(sqj23, sqj.z, sqj.w);

    float* orow = out + ((size_t)b * N + i0) * N + j;

    #pragma unroll
    for (int ii = 0; ii < TI; ii++) {
        const ulonglong2 c0 = s_c[ii * 6 + 0];   // (ntx, nty)
        const ulonglong2 c1v = s_c[ii * 6 + 1];  // (ntz, pds)
        const ulonglong2 c2 = s_c[ii * 6 + 2];   // (npx, npy)
        const ulonglong2 c3 = s_c[ii * 6 + 3];   // (npz, c1)
        const ulonglong2 c4 = s_c[ii * 6 + 4];   // (al, be)
        const ulonglong2 c5 = s_c[ii * 6 + 5];   // (sqi, sqi)
        const ull ntx = c0.x, nty = c0.y, ntz = c1v.x, pds = c1v.y;
        const ull npx = c2.x, npy = c2.y, npz = c3.x, cc1 = c3.y;
        const ull al = c4.x, be = c4.y, sqi = c5.x;

        float4 o;

        // ---- pair 0 (j, j+1) ----
        {
            ull u, a2, s, t1, t2;
            FMA2(u, pjz01, ntz, pds);          // pds - pjz*tz
            FMA2(u, pjy01, nty, u);
            FMA2(u, pjx01, ntx, u);            // along
            MUL2(a2, u, u);                    // along^2
            FMA2(s, pjz01, npz, sqi);          // sqi - 2*pjz*piz
            FMA2(s, pjy01, npy, s);
            FMA2(s, pjx01, npx, s);            // sqi - 2*(pj.pi)
            FMA2(s, a2, cc1, s);               // + a2*(||t||^2-2)
            ADD2(s, s, sqj01);                 // + sqj  -> ns (pre-max)
            MUL2(t1, al, s);                   // alpha*ns
            MUL2(t2, be, a2);                  // beta*a2
            float t1x, t1y, t2x, t2y;
            UNPACK2(t1x, t1y, t1);
            UNPACK2(t2x, t2y, t2);
            o.x = fmaxf(t1x, 0.0f) + t2x;      // alpha>0: alpha*max(ns,0)=max(alpha*ns,0)
            o.y = fmaxf(t1y, 0.0f) + t2y;
        }
        // ---- pair 1 (j+2, j+3) ----
        {
            ull u, a2, s, t1, t2;
            FMA2(u, pjz23, ntz, pds);
            FMA2(u, pjy23, nty, u);
            FMA2(u, pjx23, ntx, u);
            MUL2(a2, u, u);
            FMA2(s, pjz23, npz, sqi);
            FMA2(s, pjy23, npy, s);
            FMA2(s, pjx23, npx, s);
            FMA2(s, a2, cc1, s);
            ADD2(s, s, sqj23);
            MUL2(t1, al, s);
            MUL2(t2, be, a2);
            float t1x, t1y, t2x, t2y;
            UNPACK2(t1x, t1y, t1);
            UNPACK2(t2x, t2y, t2);
            o.z = fmaxf(t1x, 0.0f) + t2x;
            o.w = fmaxf(t1y, 0.0f) + t2y;
        }

        __stcs(reinterpret_cast<float4*>(orow), o);   // streaming store
        orow += N;
    }
}

extern "C" void kernel_launch(void* const* d_in, const int* in_sizes, int n_in,
                              void* d_out, int out_size) {
    const float* points = (const float*)d_in[0];
    const float* pdir   = (const float*)d_in[1];
    const float* lin    = (const float*)d_in[2];
    float* out = (float*)d_out;

    const int total = in_sizes[0] / 3;                 // B*N points
    const int N = (int)((long long)out_size / total);  // out = B*N*N
    const int B = total / N;

    precompute_kernel<<<(total + 255) / 256, 256>>>(points, pdir, lin, total);

    dim3 grid((N + TPB * JV - 1) / (TPB * JV), (N + TI - 1) / TI, B);
    aniso_main_kernel<<<grid, TPB>>>(out, N);
}